// round 11
// baseline (speedup 1.0000x reference)
#include <cuda_runtime.h>
#include <cuda_fp16.h>
#include <cstdint>

#define B_ 16384
#define S_ 336
#define T_ 48
#define MROWS_ 128
#define NCTA_ (B_ / MROWS_)
#define THREADS_ 512

// smem byte offsets
#define H0A_ 0
#define H0B_ 16384
#define H1A_ 32768
#define H1B_ 49152
#define WHH0_ 65536
#define W1A_ 98304
#define W1B_ 131072
#define W0X_ 163840      // 256*48
#define XT0_ 176128      // 128*48
#define XT1_ 182272      // 128*48
#define BIAS0_ 188416    // 1024
#define BIAS1_ 189440    // 1024
#define PART_ 190464     // 128*8 floats = 4096
#define SMEM_BYTES 194560

__device__ __forceinline__ uint32_t smem_u32(const void* p) {
    uint32_t a;
    asm("{ .reg .u64 t; cvta.to.shared.u64 t, %1; cvt.u32.u64 %0, t; }" : "=r"(a) : "l"(p));
    return a;
}
__device__ __forceinline__ void sts32(uint32_t a, uint32_t v) {
    asm volatile("st.shared.u32 [%0], %1;" :: "r"(a), "r"(v) : "memory");
}
#define LDSM4(r0, r1, r2, r3, addr) \
    asm volatile("ldmatrix.sync.aligned.m8n8.x4.shared.b16 {%0,%1,%2,%3}, [%4];" \
        : "=r"(r0), "=r"(r1), "=r"(r2), "=r"(r3) : "r"(addr))

__device__ __forceinline__ void mma16816(float* d, uint32_t a0, uint32_t a1, uint32_t a2, uint32_t a3,
                                         uint32_t b0, uint32_t b1) {
    asm volatile(
        "mma.sync.aligned.m16n8k16.row.col.f32.f16.f16.f32 "
        "{%0,%1,%2,%3},{%4,%5,%6,%7},{%8,%9},{%0,%1,%2,%3};"
        : "+f"(d[0]), "+f"(d[1]), "+f"(d[2]), "+f"(d[3])
        : "r"(a0), "r"(a1), "r"(a2), "r"(a3), "r"(b0), "r"(b1));
}

__device__ __forceinline__ float tanh_a(float x) { float y; asm("tanh.approx.f32 %0,%1;" : "=f"(y) : "f"(x)); return y; }
__device__ __forceinline__ float sig_a(float x) { return fmaf(tanh_a(0.5f * x), 0.5f, 0.5f); }

// permuted gate row: smem row n -> source gate ((n>>3)&3)*64 + (n>>5)*8 + (n&7)
__device__ __forceinline__ int perm_gate(int n) {
    return ((n >> 3) & 3) * 64 + (n >> 5) * 8 + (n & 7);
}

// [256][64] fp16 tile, 128B rows, chunk swizzle c^(row&7), from fp32 row-major [256][64]
__device__ __forceinline__ void fill_wtile(uint32_t dst, const float* __restrict__ W) {
    for (int i = threadIdx.x; i < 256 * 32; i += THREADS_) {
        int n = i >> 5, p = i & 31;
        int gate = perm_gate(n);
        float2 v = *(const float2*)(W + gate * 64 + 2 * p);
        __half2 h = __floats2half2_rn(v.x, v.y);
        int chunk = p >> 2;
        sts32(dst + n * 128 + ((chunk ^ (n & 7)) << 4) + ((p & 3) << 2), *(uint32_t*)&h);
    }
}
// [256][16] fp16 tile, 48B row stride, first `incols` cols from W [256][incols], rest 0
__device__ __forceinline__ void fill_w0x(uint32_t dst, const float* __restrict__ W, int incols) {
    for (int i = threadIdx.x; i < 256 * 8; i += THREADS_) {
        int n = i >> 3, p = i & 7;
        int gate = perm_gate(n);
        int k0 = 2 * p, k1 = 2 * p + 1;
        float v0 = (k0 < incols) ? W[gate * incols + k0] : 0.0f;
        float v1 = (k1 < incols) ? W[gate * incols + k1] : 0.0f;
        __half2 h = __floats2half2_rn(v0, v1);
        sts32(dst + n * 48 + p * 4, *(uint32_t*)&h);
    }
}

// persistent B fragments: [256x64] weight tile -> 32 regs (this warp's 8 units, 4 ksteps)
__device__ __forceinline__ void load_bh(uint32_t wbase, uint32_t* bf, int ng, int lane) {
    const int mat = lane >> 3;
    const int brow = 32 * ng + 8 * (mat >> 1) + (lane & 7);
    const int bxor = lane & 7;
    const int bch = mat & 1;
#pragma unroll
    for (int ks = 0; ks < 4; ks++) {
        uint32_t aA = wbase + brow * 128 + (((2 * ks + bch) ^ bxor) << 4);
        LDSM4(bf[ks * 8 + 0], bf[ks * 8 + 1], bf[ks * 8 + 2], bf[ks * 8 + 3], aA);
        uint32_t aB = wbase + (brow + 16) * 128 + (((2 * ks + bch) ^ bxor) << 4);
        LDSM4(bf[ks * 8 + 4], bf[ks * 8 + 5], bf[ks * 8 + 6], bf[ks * 8 + 7], aB);
    }
}
// x-weight tile [256x16] -> 8 regs
__device__ __forceinline__ void load_bx(uint32_t wbase, uint32_t* bf, int ng, int lane) {
    const int mat = lane >> 3;
    const int brow = 32 * ng + 8 * (mat >> 1) + (lane & 7);
    const int bch = mat & 1;
    uint32_t aA = wbase + brow * 48 + bch * 16;
    LDSM4(bf[0], bf[1], bf[2], bf[3], aA);
    uint32_t aB = wbase + (brow + 16) * 48 + bch * 16;
    LDSM4(bf[4], bf[5], bf[6], bf[7], aB);
}

// one layer tick, fine-grained interleave: epilogue cells of block k are placed
// BETWEEN the MMA chunks of block k+1 in program order, so tensor and MUFU
// pipes both have issueable work at every point in the stream.
// Epilogue math is the PROVEN fp32 path (rel_err 9.2e-5) — only the h store is half.
template <bool XPART, bool FC>
__device__ __forceinline__ void lstm_tick(uint32_t a1base, uint32_t a2base,
                                          const uint32_t* bf1, const uint32_t* bf2x,
                                          uint32_t w2base,
                                          uint32_t hwr, const float* biasp, float* cst,
                                          int ng, int lane,
                                          float fw0, float fw1, float* part) {
    const int rowp = lane & 15;
    const int kh = lane >> 4;
    const int uA = 8 * ng + (lane & 3) * 2;
    const int mat = lane >> 3;
    const int brow = 32 * ng + 8 * (mat >> 1) + (lane & 7);
    const int bxor = lane & 7;
    const int bch = mat & 1;

    float acc[2][4][4];
    float hh[4];

    auto init_acc = [&](int buf) {
#pragma unroll
        for (int g = 0; g < 4; g++) {
            float2 bv = *(const float2*)(biasp + g * 64 + uA);
            acc[buf][g][0] = bv.x; acc[buf][g][1] = bv.y;
            acc[buf][g][2] = bv.x; acc[buf][g][3] = bv.y;
        }
    };

    // chunk: XPART -> 0..3 = h ksteps (bf1), 4 = x (bf2x)
    //        else  -> 0..3 = first h (bf1), 4..7 = second h (inline B reload from w2base)
    auto mma_chunk = [&](int mi, int buf, int ch) {
        const int rowbase = mi * 16;
        float (*a)[4] = acc[buf];
        uint32_t a0, a1, a2, a3;
        if (XPART && ch == 4) {
            uint32_t aa = a2base + (rowbase + rowp) * 48 + kh * 16;
            LDSM4(a0, a1, a2, a3, aa);
#pragma unroll
            for (int j = 0; j < 4; j++)
                mma16816(a[j], a0, a1, a2, a3, bf2x[j * 2], bf2x[j * 2 + 1]);
        } else if (ch < 4) {
            const int ks = ch;
            uint32_t aa = a1base + (rowbase + rowp) * 128 + (((2 * ks + kh) ^ (rowp & 7)) << 4);
            LDSM4(a0, a1, a2, a3, aa);
#pragma unroll
            for (int j = 0; j < 4; j++)
                mma16816(a[j], a0, a1, a2, a3, bf1[ks * 8 + j * 2], bf1[ks * 8 + j * 2 + 1]);
        } else {
            const int ks = ch - 4;
            uint32_t aa = a2base + (rowbase + rowp) * 128 + (((2 * ks + kh) ^ (rowp & 7)) << 4);
            LDSM4(a0, a1, a2, a3, aa);
            uint32_t b0, b1, b2, b3, b4, b5, b6, b7;
            uint32_t wA = w2base + brow * 128 + (((2 * ks + bch) ^ bxor) << 4);
            LDSM4(b0, b1, b2, b3, wA);
            uint32_t wB = w2base + (brow + 16) * 128 + (((2 * ks + bch) ^ bxor) << 4);
            LDSM4(b4, b5, b6, b7, wB);
            mma16816(a[0], a0, a1, a2, a3, b0, b1);
            mma16816(a[1], a0, a1, a2, a3, b2, b3);
            mma16816(a[2], a0, a1, a2, a3, b4, b5);
            mma16816(a[3], a0, a1, a2, a3, b6, b7);
        }
    };

    auto epi_cell = [&](int mi, int buf, int d) {
        float (*a)[4] = acc[buf];
        float i_ = sig_a(a[0][d]);
        float f_ = sig_a(a[1][d]);
        float g_ = tanh_a(a[2][d]);
        float o_ = sig_a(a[3][d]);
        float c = fmaf(f_, cst[mi * 4 + d], i_ * g_);
        cst[mi * 4 + d] = c;
        hh[d] = o_ * tanh_a(c);
    };

    auto store_pair = [&](int mi, int p) {  // p=0 -> cells 0,1 ; p=1 -> cells 2,3
        uint32_t cx = ((uint32_t)(ng ^ ((lane >> 2) & 7))) << 4;
        uint32_t ba = hwr + (mi * 16 + (lane >> 2)) * 128 + cx + (lane & 3) * 4 + p * 8 * 128;
        __half2 pk = __floats2half2_rn(hh[2 * p], hh[2 * p + 1]);
        sts32(ba, *(uint32_t*)&pk);
        if (FC) {
            float pr = fmaf(hh[2 * p], fw0, hh[2 * p + 1] * fw1);
            pr += __shfl_xor_sync(0xffffffffu, pr, 1);
            pr += __shfl_xor_sync(0xffffffffu, pr, 2);
            if ((lane & 3) == 0)
                part[(mi * 16 + (lane >> 2) + p * 8) * 8 + ng] = pr;
        }
    };

    // prologue: block 0 fully
    init_acc(0);
    if (XPART) {
#pragma unroll
        for (int ch = 0; ch < 5; ch++) mma_chunk(0, 0, ch);
    } else {
#pragma unroll
        for (int ch = 0; ch < 8; ch++) mma_chunk(0, 0, ch);
    }

#pragma unroll
    for (int mii = 0; mii < 8; mii++) {
        const int buf = mii & 1;
        const int nbuf = buf ^ 1;
        if (mii < 7) {
            const int nb = mii + 1;
            init_acc(nbuf);
            if (XPART) {
                mma_chunk(nb, nbuf, 0); epi_cell(mii, buf, 0);
                mma_chunk(nb, nbuf, 1); epi_cell(mii, buf, 1); store_pair(mii, 0);
                mma_chunk(nb, nbuf, 2); epi_cell(mii, buf, 2);
                mma_chunk(nb, nbuf, 3); epi_cell(mii, buf, 3); store_pair(mii, 1);
                mma_chunk(nb, nbuf, 4);
            } else {
                mma_chunk(nb, nbuf, 0); epi_cell(mii, buf, 0);
                mma_chunk(nb, nbuf, 1);
                mma_chunk(nb, nbuf, 2); epi_cell(mii, buf, 1); store_pair(mii, 0);
                mma_chunk(nb, nbuf, 3);
                mma_chunk(nb, nbuf, 4); epi_cell(mii, buf, 2);
                mma_chunk(nb, nbuf, 5);
                mma_chunk(nb, nbuf, 6); epi_cell(mii, buf, 3); store_pair(mii, 1);
                mma_chunk(nb, nbuf, 7);
            }
        } else {
            epi_cell(mii, buf, 0);
            epi_cell(mii, buf, 1); store_pair(mii, 0);
            epi_cell(mii, buf, 2);
            epi_cell(mii, buf, 3); store_pair(mii, 1);
        }
    }
}

__global__ void __launch_bounds__(THREADS_, 1)
seq2seq_pipe(const float* __restrict__ src,
             const float* __restrict__ eWih0, const float* __restrict__ eWhh0,
             const float* __restrict__ ebih0, const float* __restrict__ ebhh0,
             const float* __restrict__ eWih1, const float* __restrict__ eWhh1,
             const float* __restrict__ ebih1, const float* __restrict__ ebhh1,
             const float* __restrict__ dWih0, const float* __restrict__ dWhh0,
             const float* __restrict__ dbih0, const float* __restrict__ dbhh0,
             const float* __restrict__ dWih1, const float* __restrict__ dWhh1,
             const float* __restrict__ dbih1, const float* __restrict__ dbhh1,
             const float* __restrict__ fcW, const float* __restrict__ fcb,
             float* __restrict__ out) {
    extern __shared__ char smc[];
    const uint32_t sb = smem_u32(smc);
    const int tid = threadIdx.x;
    const int lane = tid & 31;
    const int warp = tid >> 5;
    const bool isL0 = warp < 8;
    const int ng = isL0 ? warp : warp - 8;
    const int row0 = blockIdx.x * MROWS_;

    // zero h buffers and XT buffers
    {
        uint4 z = make_uint4(0, 0, 0, 0);
        uint4* p0 = (uint4*)smc;
        for (int i = tid; i < 65536 / 16; i += THREADS_) p0[i] = z;
        uint4* p1 = (uint4*)(smc + XT0_);
        for (int i = tid; i < 12288 / 16; i += THREADS_) p1[i] = z;
    }
    __syncthreads();

    fill_wtile(sb + WHH0_, eWhh0);
    fill_wtile(sb + W1A_, eWih1);
    fill_wtile(sb + W1B_, eWhh1);
    fill_w0x(sb + W0X_, eWih0, 5);
    for (int i = tid; i < 256; i += THREADS_) {
        ((float*)(smc + BIAS0_))[i] = __ldg(ebih0 + i) + __ldg(ebhh0 + i);
        ((float*)(smc + BIAS1_))[i] = __ldg(ebih1 + i) + __ldg(ebhh1 + i);
    }
    const float* srcRow = src + (size_t)(row0 + tid) * S_ * 5;
    if (tid < MROWS_) {  // x(0) -> XT0
        uint32_t xb = sb + XT0_ + tid * 48;
        __half2 a01 = __floats2half2_rn(__ldg(srcRow + 0), __ldg(srcRow + 1));
        __half2 a23 = __floats2half2_rn(__ldg(srcRow + 2), __ldg(srcRow + 3));
        __half2 a4z = __floats2half2_rn(__ldg(srcRow + 4), 0.0f);
        sts32(xb, *(uint32_t*)&a01);
        sts32(xb + 4, *(uint32_t*)&a23);
        sts32(xb + 8, *(uint32_t*)&a4z);
    }
    __syncthreads();

    // persistent weight fragments: bf1 hoisted for both layers; bf2 hoisted only for L0 (x-weights)
    uint32_t bf1[32], bf2x[8];
    if (isL0) {
        load_bh(sb + WHH0_, bf1, ng, lane);
        load_bx(sb + W0X_, bf2x, ng, lane);
    } else {
        load_bh(sb + W1A_, bf1, ng, lane);
    }

    float cst[32];
#pragma unroll
    for (int j = 0; j < 32; j++) cst[j] = 0.0f;

    const float* bias0 = (const float*)(smc + BIAS0_);
    const float* bias1 = (const float*)(smc + BIAS1_);

    // ============ encoder pipeline: ticks k=0..S ============
    for (int k = 0; k <= S_; k++) {
        const uint32_t h0r = sb + ((k & 1) ? H0A_ : H0B_);
        const uint32_t h0w = sb + ((k & 1) ? H0B_ : H0A_);
        const uint32_t h1r = sb + ((k & 1) ? H1B_ : H1A_);
        const uint32_t h1w = sb + ((k & 1) ? H1A_ : H1B_);
        const uint32_t xtr = sb + ((k & 1) ? XT1_ : XT0_);
        const uint32_t xtw = sb + ((k & 1) ? XT0_ : XT1_);

        float x0, x1, x2, x3, x4;
        const bool pf = (tid < MROWS_) && (k + 1 < S_);
        if (pf) {
            const float* xp = srcRow + (size_t)(k + 1) * 5;
            x0 = __ldg(xp + 0); x1 = __ldg(xp + 1); x2 = __ldg(xp + 2);
            x3 = __ldg(xp + 3); x4 = __ldg(xp + 4);
        }
        if (isL0) {
            if (k < S_)
                lstm_tick<true, false>(h0r, xtr, bf1, bf2x, 0, h0w, bias0, cst, ng, lane, 0.f, 0.f, nullptr);
        } else {
            if (k >= 1)
                lstm_tick<false, false>(h0r, h1r, bf1, nullptr, sb + W1B_, h1w, bias1, cst, ng, lane, 0.f, 0.f, nullptr);
        }
        if (pf) {
            __half2 a01 = __floats2half2_rn(x0, x1);
            __half2 a23 = __floats2half2_rn(x2, x3);
            __half2 a4z = __floats2half2_rn(x4, 0.0f);
            uint32_t xb = xtw + tid * 48;
            sts32(xb, *(uint32_t*)&a01);
            sts32(xb + 4, *(uint32_t*)&a23);
            sts32(xb + 8, *(uint32_t*)&a4z);
        }
        __syncthreads();
    }

    // ============ decoder weight swap ============
    fill_wtile(sb + WHH0_, dWhh0);
    fill_wtile(sb + W1A_, dWih1);
    fill_wtile(sb + W1B_, dWhh1);
    fill_w0x(sb + W0X_, dWih0, 1);
    for (int i = tid; i < 256; i += THREADS_) {
        ((float*)(smc + BIAS0_))[i] = __ldg(dbih0 + i) + __ldg(dbhh0 + i);
        ((float*)(smc + BIAS1_))[i] = __ldg(dbih1 + i) + __ldg(dbhh1 + i);
    }
    {
        uint4 z = make_uint4(0, 0, 0, 0);
        uint4* p1 = (uint4*)(smc + XT0_);
        for (int i = tid; i < 12288 / 16; i += THREADS_) p1[i] = z;
    }
    float fw0 = 0.f, fw1 = 0.f;
    if (!isL0) {
        const int uAa = 8 * ng + (lane & 3) * 2;
        fw0 = __ldg(fcW + uAa);
        fw1 = __ldg(fcW + uAa + 1);
    }
    const float fcb_r = __ldg(fcb);
    __syncthreads();

    if (isL0) {
        load_bh(sb + WHH0_, bf1, ng, lane);
        load_bx(sb + W0X_, bf2x, ng, lane);
    } else {
        load_bh(sb + W1A_, bf1, ng, lane);
    }
    if (tid < MROWS_) {  // x(0) = src[:, -1, 3] -> XT0
        float xd = __ldg(srcRow + (size_t)(S_ - 1) * 5 + 3);
        __half2 hx = __floats2half2_rn(xd, 0.0f);
        sts32(sb + XT0_ + tid * 48, *(uint32_t*)&hx);
    }
    __syncthreads();

    float* part = (float*)(smc + PART_);

    // ============ decoder: sequential phases ============
    for (int t = 0; t < T_; t++) {
        const uint32_t h0r = sb + ((t & 1) ? H0A_ : H0B_);
        const uint32_t h0w = sb + ((t & 1) ? H0B_ : H0A_);
        const uint32_t h1r = sb + ((t & 1) ? H1A_ : H1B_);
        const uint32_t h1w = sb + ((t & 1) ? H1B_ : H1A_);
        const uint32_t xtr = sb + ((t & 1) ? XT1_ : XT0_);

        if (isL0)
            lstm_tick<true, false>(h0r, xtr, bf1, bf2x, 0, h0w, bias0, cst, ng, lane, 0.f, 0.f, nullptr);
        __syncthreads();
        if (!isL0)
            lstm_tick<false, true>(h0w, h1r, bf1, nullptr, sb + W1B_, h1w, bias1, cst, ng, lane, fw0, fw1, part);
        __syncthreads();
        if (tid < MROWS_) {
            float4 q0 = *(float4*)(part + tid * 8);
            float4 q1 = *(float4*)(part + tid * 8 + 4);
            float x = q0.x + q0.y + q0.z + q0.w + q1.x + q1.y + q1.z + q1.w + fcb_r;
            out[(size_t)(row0 + tid) * T_ + t] = x;
            __half2 hx = __floats2half2_rn(x, 0.0f);
            sts32(sb + ((t & 1) ? XT0_ : XT1_) + tid * 48, *(uint32_t*)&hx);
        }
        __syncthreads();
    }
}

extern "C" void kernel_launch(void* const* d_in, const int* in_sizes, int n_in,
                              void* d_out, int out_size) {
    (void)in_sizes; (void)n_in; (void)out_size;
    cudaFuncSetAttribute(seq2seq_pipe, cudaFuncAttributeMaxDynamicSharedMemorySize, SMEM_BYTES);
    seq2seq_pipe<<<NCTA_, THREADS_, SMEM_BYTES>>>(
        (const float*)d_in[0],
        (const float*)d_in[1], (const float*)d_in[2], (const float*)d_in[3], (const float*)d_in[4],
        (const float*)d_in[5], (const float*)d_in[6], (const float*)d_in[7], (const float*)d_in[8],
        (const float*)d_in[9], (const float*)d_in[10], (const float*)d_in[11], (const float*)d_in[12],
        (const float*)d_in[13], (const float*)d_in[14], (const float*)d_in[15], (const float*)d_in[16],
        (const float*)d_in[17], (const float*)d_in[18],
        (float*)d_out);
}

// round 12
// speedup vs baseline: 1.0427x; 1.0427x over previous
#include <cuda_runtime.h>
#include <cuda_fp16.h>
#include <cstdint>

#define B_ 16384
#define S_ 336
#define T_ 48
#define NCTA_ 148
#define THREADS_ 512
#define MAXBLK_ 7

// smem byte offsets (h tiles sized for up to 112 rows; keep 128-row stride layout)
#define H0A_ 0
#define H0B_ 16384
#define H1A_ 32768
#define H1B_ 49152
#define WHH0_ 65536
#define W1A_ 98304
#define W1B_ 131072
#define W0X_ 163840      // 256*48
#define XT0_ 176128      // 128*48
#define XT1_ 182272      // 128*48
#define BIAS0_ 188416    // 1024
#define BIAS1_ 189440    // 1024
#define PART_ 190464     // 128*8 floats = 4096
#define SMEM_BYTES 194560

__device__ __forceinline__ uint32_t smem_u32(const void* p) {
    uint32_t a;
    asm("{ .reg .u64 t; cvta.to.shared.u64 t, %1; cvt.u32.u64 %0, t; }" : "=r"(a) : "l"(p));
    return a;
}
__device__ __forceinline__ void sts32(uint32_t a, uint32_t v) {
    asm volatile("st.shared.u32 [%0], %1;" :: "r"(a), "r"(v) : "memory");
}
#define LDSM4(r0, r1, r2, r3, addr) \
    asm volatile("ldmatrix.sync.aligned.m8n8.x4.shared.b16 {%0,%1,%2,%3}, [%4];" \
        : "=r"(r0), "=r"(r1), "=r"(r2), "=r"(r3) : "r"(addr))

__device__ __forceinline__ void mma16816(float* d, uint32_t a0, uint32_t a1, uint32_t a2, uint32_t a3,
                                         uint32_t b0, uint32_t b1) {
    asm volatile(
        "mma.sync.aligned.m16n8k16.row.col.f32.f16.f16.f32 "
        "{%0,%1,%2,%3},{%4,%5,%6,%7},{%8,%9},{%0,%1,%2,%3};"
        : "+f"(d[0]), "+f"(d[1]), "+f"(d[2]), "+f"(d[3])
        : "r"(a0), "r"(a1), "r"(a2), "r"(a3), "r"(b0), "r"(b1));
}

__device__ __forceinline__ float tanh_a(float x) { float y; asm("tanh.approx.f32 %0,%1;" : "=f"(y) : "f"(x)); return y; }
__device__ __forceinline__ float sig_a(float x) { return fmaf(tanh_a(0.5f * x), 0.5f, 0.5f); }

// permuted gate row: smem row n -> source gate ((n>>3)&3)*64 + (n>>5)*8 + (n&7)
__device__ __forceinline__ int perm_gate(int n) {
    return ((n >> 3) & 3) * 64 + (n >> 5) * 8 + (n & 7);
}

// [256][64] fp16 tile, 128B rows, chunk swizzle c^(row&7), from fp32 row-major [256][64]
__device__ __forceinline__ void fill_wtile(uint32_t dst, const float* __restrict__ W) {
    for (int i = threadIdx.x; i < 256 * 32; i += THREADS_) {
        int n = i >> 5, p = i & 31;
        int gate = perm_gate(n);
        float2 v = *(const float2*)(W + gate * 64 + 2 * p);
        __half2 h = __floats2half2_rn(v.x, v.y);
        int chunk = p >> 2;
        sts32(dst + n * 128 + ((chunk ^ (n & 7)) << 4) + ((p & 3) << 2), *(uint32_t*)&h);
    }
}
// [256][16] fp16 tile, 48B row stride, first `incols` cols from W [256][incols], rest 0
__device__ __forceinline__ void fill_w0x(uint32_t dst, const float* __restrict__ W, int incols) {
    for (int i = threadIdx.x; i < 256 * 8; i += THREADS_) {
        int n = i >> 3, p = i & 7;
        int gate = perm_gate(n);
        int k0 = 2 * p, k1 = 2 * p + 1;
        float v0 = (k0 < incols) ? W[gate * incols + k0] : 0.0f;
        float v1 = (k1 < incols) ? W[gate * incols + k1] : 0.0f;
        __half2 h = __floats2half2_rn(v0, v1);
        sts32(dst + n * 48 + p * 4, *(uint32_t*)&h);
    }
}

// persistent B fragments: [256x64] weight tile -> 32 regs (this warp's 8 units, 4 ksteps)
__device__ __forceinline__ void load_bh(uint32_t wbase, uint32_t* bf, int ng, int lane) {
    const int mat = lane >> 3;
    const int brow = 32 * ng + 8 * (mat >> 1) + (lane & 7);
    const int bxor = lane & 7;
    const int bch = mat & 1;
#pragma unroll
    for (int ks = 0; ks < 4; ks++) {
        uint32_t aA = wbase + brow * 128 + (((2 * ks + bch) ^ bxor) << 4);
        LDSM4(bf[ks * 8 + 0], bf[ks * 8 + 1], bf[ks * 8 + 2], bf[ks * 8 + 3], aA);
        uint32_t aB = wbase + (brow + 16) * 128 + (((2 * ks + bch) ^ bxor) << 4);
        LDSM4(bf[ks * 8 + 4], bf[ks * 8 + 5], bf[ks * 8 + 6], bf[ks * 8 + 7], aB);
    }
}
// x-weight tile [256x16] -> 8 regs
__device__ __forceinline__ void load_bx(uint32_t wbase, uint32_t* bf, int ng, int lane) {
    const int mat = lane >> 3;
    const int brow = 32 * ng + 8 * (mat >> 1) + (lane & 7);
    const int bch = mat & 1;
    uint32_t aA = wbase + brow * 48 + bch * 16;
    LDSM4(bf[0], bf[1], bf[2], bf[3], aA);
    uint32_t aB = wbase + (brow + 16) * 48 + bch * 16;
    LDSM4(bf[4], bf[5], bf[6], bf[7], aB);
}

// one layer tick over nblk row-blocks (runtime, <= MAXBLK_), software-pipelined with
// statically-indexed double buffers. Epilogue math = proven fp32 path; h store is half.
template <bool XPART, bool FC>
__device__ __forceinline__ void lstm_tick(uint32_t a1base, uint32_t a2base,
                                          const uint32_t* bf1, const uint32_t* bf2x,
                                          uint32_t w2base,
                                          uint32_t hwr, const float* biasp, float* cst,
                                          int ng, int lane, int nblk,
                                          float fw0, float fw1, float* part) {
    const int rowp = lane & 15;
    const int kh = lane >> 4;
    const int uA = 8 * ng + (lane & 3) * 2;
    const int mat = lane >> 3;
    const int brow = 32 * ng + 8 * (mat >> 1) + (lane & 7);
    const int bxor = lane & 7;
    const int bch = mat & 1;

    float accA[4][4], accB[4][4];

    auto init_acc = [&](float (&a)[4][4]) {
#pragma unroll
        for (int g = 0; g < 4; g++) {
            float2 bv = *(const float2*)(biasp + g * 64 + uA);
            a[g][0] = bv.x; a[g][1] = bv.y;
            a[g][2] = bv.x; a[g][3] = bv.y;
        }
    };

    auto mma_block = [&](int mi, float (&a)[4][4]) {
        const int rowbase = mi * 16;
        uint32_t a0, a1, a2, a3;
#pragma unroll
        for (int ks = 0; ks < 4; ks++) {
            uint32_t aa = a1base + (rowbase + rowp) * 128 + (((2 * ks + kh) ^ (rowp & 7)) << 4);
            LDSM4(a0, a1, a2, a3, aa);
#pragma unroll
            for (int j = 0; j < 4; j++)
                mma16816(a[j], a0, a1, a2, a3, bf1[ks * 8 + j * 2], bf1[ks * 8 + j * 2 + 1]);
        }
        if (XPART) {
            uint32_t aa = a2base + (rowbase + rowp) * 48 + kh * 16;
            LDSM4(a0, a1, a2, a3, aa);
#pragma unroll
            for (int j = 0; j < 4; j++)
                mma16816(a[j], a0, a1, a2, a3, bf2x[j * 2], bf2x[j * 2 + 1]);
        } else {
#pragma unroll
            for (int ks = 0; ks < 4; ks++) {
                uint32_t aa = a2base + (rowbase + rowp) * 128 + (((2 * ks + kh) ^ (rowp & 7)) << 4);
                LDSM4(a0, a1, a2, a3, aa);
                uint32_t b0, b1, b2, b3, b4, b5, b6, b7;
                uint32_t wA = w2base + brow * 128 + (((2 * ks + bch) ^ bxor) << 4);
                LDSM4(b0, b1, b2, b3, wA);
                uint32_t wB = w2base + (brow + 16) * 128 + (((2 * ks + bch) ^ bxor) << 4);
                LDSM4(b4, b5, b6, b7, wB);
                mma16816(a[0], a0, a1, a2, a3, b0, b1);
                mma16816(a[1], a0, a1, a2, a3, b2, b3);
                mma16816(a[2], a0, a1, a2, a3, b4, b5);
                mma16816(a[3], a0, a1, a2, a3, b6, b7);
            }
        }
    };

    auto epi = [&](int mi, float (&a)[4][4]) {
        float h[4];
#pragma unroll
        for (int d = 0; d < 4; d++) {
            float i_ = sig_a(a[0][d]);
            float f_ = sig_a(a[1][d]);
            float g_ = tanh_a(a[2][d]);
            float o_ = sig_a(a[3][d]);
            float c = fmaf(f_, cst[mi * 4 + d], i_ * g_);
            cst[mi * 4 + d] = c;
            h[d] = o_ * tanh_a(c);
        }
        uint32_t cx = ((uint32_t)(ng ^ ((lane >> 2) & 7))) << 4;
        uint32_t ba = hwr + (mi * 16 + (lane >> 2)) * 128 + cx + (lane & 3) * 4;
        __half2 p1 = __floats2half2_rn(h[0], h[1]);
        sts32(ba, *(uint32_t*)&p1);
        __half2 p2 = __floats2half2_rn(h[2], h[3]);
        sts32(ba + 8 * 128, *(uint32_t*)&p2);
        if (FC) {
            float pA = fmaf(h[0], fw0, h[1] * fw1);
            float pB = fmaf(h[2], fw0, h[3] * fw1);
            pA += __shfl_xor_sync(0xffffffffu, pA, 1);
            pA += __shfl_xor_sync(0xffffffffu, pA, 2);
            pB += __shfl_xor_sync(0xffffffffu, pB, 1);
            pB += __shfl_xor_sync(0xffffffffu, pB, 2);
            if ((lane & 3) == 0) {
                int r = mi * 16 + (lane >> 2);
                part[r * 8 + ng] = pA;
                part[(r + 8) * 8 + ng] = pB;
            }
        }
    };

    // pipelined over block pairs; all block indices are compile-time constants,
    // guards are warp-uniform runtime comparisons.
    init_acc(accA);
    mma_block(0, accA);
#pragma unroll
    for (int p = 0; p < (MAXBLK_ + 1) / 2; p++) {
        const int b0 = 2 * p, b1 = 2 * p + 1, b2 = 2 * p + 2;
        if (b0 >= nblk) break;
        if (b1 < nblk) { init_acc(accB); mma_block(b1, accB); }
        epi(b0, accA);
        if (b1 < nblk) {
            if (b2 < nblk) { init_acc(accA); mma_block(b2, accA); }
            epi(b1, accB);
        }
    }
}

__global__ void __launch_bounds__(THREADS_, 1)
seq2seq_pipe(const float* __restrict__ src,
             const float* __restrict__ eWih0, const float* __restrict__ eWhh0,
             const float* __restrict__ ebih0, const float* __restrict__ ebhh0,
             const float* __restrict__ eWih1, const float* __restrict__ eWhh1,
             const float* __restrict__ ebih1, const float* __restrict__ ebhh1,
             const float* __restrict__ dWih0, const float* __restrict__ dWhh0,
             const float* __restrict__ dbih0, const float* __restrict__ dbhh0,
             const float* __restrict__ dWih1, const float* __restrict__ dWhh1,
             const float* __restrict__ dbih1, const float* __restrict__ dbhh1,
             const float* __restrict__ fcW, const float* __restrict__ fcb,
             float* __restrict__ out) {
    extern __shared__ char smc[];
    const uint32_t sb = smem_u32(smc);
    const int tid = threadIdx.x;
    const int lane = tid & 31;
    const int warp = tid >> 5;
    const bool isL0 = warp < 8;
    const int ng = isL0 ? warp : warp - 8;
    // uneven persistent grid: 1024 row-blocks = 136 CTAs x 7 + 12 CTAs x 6
    const int bid = blockIdx.x;
    const int nblk = (bid < 136) ? 7 : 6;
    const int row0 = (bid < 136) ? bid * 112 : 136 * 112 + (bid - 136) * 96;
    const int rows = nblk * 16;

    // zero h buffers and XT buffers
    {
        uint4 z = make_uint4(0, 0, 0, 0);
        uint4* p0 = (uint4*)smc;
        for (int i = tid; i < 65536 / 16; i += THREADS_) p0[i] = z;
        uint4* p1 = (uint4*)(smc + XT0_);
        for (int i = tid; i < 12288 / 16; i += THREADS_) p1[i] = z;
    }
    __syncthreads();

    fill_wtile(sb + WHH0_, eWhh0);
    fill_wtile(sb + W1A_, eWih1);
    fill_wtile(sb + W1B_, eWhh1);
    fill_w0x(sb + W0X_, eWih0, 5);
    for (int i = tid; i < 256; i += THREADS_) {
        ((float*)(smc + BIAS0_))[i] = __ldg(ebih0 + i) + __ldg(ebhh0 + i);
        ((float*)(smc + BIAS1_))[i] = __ldg(ebih1 + i) + __ldg(ebhh1 + i);
    }
    const float* srcRow = src + (size_t)(row0 + tid) * S_ * 5;
    if (tid < rows) {  // x(0) -> XT0
        uint32_t xb = sb + XT0_ + tid * 48;
        __half2 a01 = __floats2half2_rn(__ldg(srcRow + 0), __ldg(srcRow + 1));
        __half2 a23 = __floats2half2_rn(__ldg(srcRow + 2), __ldg(srcRow + 3));
        __half2 a4z = __floats2half2_rn(__ldg(srcRow + 4), 0.0f);
        sts32(xb, *(uint32_t*)&a01);
        sts32(xb + 4, *(uint32_t*)&a23);
        sts32(xb + 8, *(uint32_t*)&a4z);
    }
    __syncthreads();

    // persistent weight fragments: bf1 hoisted for both layers; bf2 hoisted only for L0 (x-weights)
    uint32_t bf1[32], bf2x[8];
    if (isL0) {
        load_bh(sb + WHH0_, bf1, ng, lane);
        load_bx(sb + W0X_, bf2x, ng, lane);
    } else {
        load_bh(sb + W1A_, bf1, ng, lane);
    }

    float cst[4 * MAXBLK_];
#pragma unroll
    for (int j = 0; j < 4 * MAXBLK_; j++) cst[j] = 0.0f;

    const float* bias0 = (const float*)(smc + BIAS0_);
    const float* bias1 = (const float*)(smc + BIAS1_);

    // ============ encoder pipeline: ticks k=0..S ============
    for (int k = 0; k <= S_; k++) {
        const uint32_t h0r = sb + ((k & 1) ? H0A_ : H0B_);
        const uint32_t h0w = sb + ((k & 1) ? H0B_ : H0A_);
        const uint32_t h1r = sb + ((k & 1) ? H1B_ : H1A_);
        const uint32_t h1w = sb + ((k & 1) ? H1A_ : H1B_);
        const uint32_t xtr = sb + ((k & 1) ? XT1_ : XT0_);
        const uint32_t xtw = sb + ((k & 1) ? XT0_ : XT1_);

        float x0, x1, x2, x3, x4;
        const bool pf = (tid < rows) && (k + 1 < S_);
        if (pf) {
            const float* xp = srcRow + (size_t)(k + 1) * 5;
            x0 = __ldg(xp + 0); x1 = __ldg(xp + 1); x2 = __ldg(xp + 2);
            x3 = __ldg(xp + 3); x4 = __ldg(xp + 4);
        }
        if (isL0) {
            if (k < S_)
                lstm_tick<true, false>(h0r, xtr, bf1, bf2x, 0, h0w, bias0, cst, ng, lane, nblk, 0.f, 0.f, nullptr);
        } else {
            if (k >= 1)
                lstm_tick<false, false>(h0r, h1r, bf1, nullptr, sb + W1B_, h1w, bias1, cst, ng, lane, nblk, 0.f, 0.f, nullptr);
        }
        if (pf) {
            __half2 a01 = __floats2half2_rn(x0, x1);
            __half2 a23 = __floats2half2_rn(x2, x3);
            __half2 a4z = __floats2half2_rn(x4, 0.0f);
            uint32_t xb = xtw + tid * 48;
            sts32(xb, *(uint32_t*)&a01);
            sts32(xb + 4, *(uint32_t*)&a23);
            sts32(xb + 8, *(uint32_t*)&a4z);
        }
        __syncthreads();
    }

    // ============ decoder weight swap ============
    fill_wtile(sb + WHH0_, dWhh0);
    fill_wtile(sb + W1A_, dWih1);
    fill_wtile(sb + W1B_, dWhh1);
    fill_w0x(sb + W0X_, dWih0, 1);
    for (int i = tid; i < 256; i += THREADS_) {
        ((float*)(smc + BIAS0_))[i] = __ldg(dbih0 + i) + __ldg(dbhh0 + i);
        ((float*)(smc + BIAS1_))[i] = __ldg(dbih1 + i) + __ldg(dbhh1 + i);
    }
    {
        uint4 z = make_uint4(0, 0, 0, 0);
        uint4* p1 = (uint4*)(smc + XT0_);
        for (int i = tid; i < 12288 / 16; i += THREADS_) p1[i] = z;
    }
    float fw0 = 0.f, fw1 = 0.f;
    if (!isL0) {
        const int uAa = 8 * ng + (lane & 3) * 2;
        fw0 = __ldg(fcW + uAa);
        fw1 = __ldg(fcW + uAa + 1);
    }
    const float fcb_r = __ldg(fcb);
    __syncthreads();

    if (isL0) {
        load_bh(sb + WHH0_, bf1, ng, lane);
        load_bx(sb + W0X_, bf2x, ng, lane);
    } else {
        load_bh(sb + W1A_, bf1, ng, lane);
    }
    if (tid < rows) {  // x(0) = src[:, -1, 3] -> XT0
        float xd = __ldg(srcRow + (size_t)(S_ - 1) * 5 + 3);
        __half2 hx = __floats2half2_rn(xd, 0.0f);
        sts32(sb + XT0_ + tid * 48, *(uint32_t*)&hx);
    }
    __syncthreads();

    float* part = (float*)(smc + PART_);

    // ============ decoder: sequential phases ============
    for (int t = 0; t < T_; t++) {
        const uint32_t h0r = sb + ((t & 1) ? H0A_ : H0B_);
        const uint32_t h0w = sb + ((t & 1) ? H0B_ : H0A_);
        const uint32_t h1r = sb + ((t & 1) ? H1A_ : H1B_);
        const uint32_t h1w = sb + ((t & 1) ? H1B_ : H1A_);
        const uint32_t xtr = sb + ((t & 1) ? XT1_ : XT0_);

        if (isL0)
            lstm_tick<true, false>(h0r, xtr, bf1, bf2x, 0, h0w, bias0, cst, ng, lane, nblk, 0.f, 0.f, nullptr);
        __syncthreads();
        if (!isL0)
            lstm_tick<false, true>(h0w, h1r, bf1, nullptr, sb + W1B_, h1w, bias1, cst, ng, lane, nblk, fw0, fw1, part);
        __syncthreads();
        if (tid < rows) {
            float4 q0 = *(float4*)(part + tid * 8);
            float4 q1 = *(float4*)(part + tid * 8 + 4);
            float x = q0.x + q0.y + q0.z + q0.w + q1.x + q1.y + q1.z + q1.w + fcb_r;
            out[(size_t)(row0 + tid) * T_ + t] = x;
            __half2 hx = __floats2half2_rn(x, 0.0f);
            sts32(sb + ((t & 1) ? XT0_ : XT1_) + tid * 48, *(uint32_t*)&hx);
        }
        __syncthreads();
    }
}

extern "C" void kernel_launch(void* const* d_in, const int* in_sizes, int n_in,
                              void* d_out, int out_size) {
    (void)in_sizes; (void)n_in; (void)out_size;
    cudaFuncSetAttribute(seq2seq_pipe, cudaFuncAttributeMaxDynamicSharedMemorySize, SMEM_BYTES);
    seq2seq_pipe<<<NCTA_, THREADS_, SMEM_BYTES>>>(
        (const float*)d_in[0],
        (const float*)d_in[1], (const float*)d_in[2], (const float*)d_in[3], (const float*)d_in[4],
        (const float*)d_in[5], (const float*)d_in[6], (const float*)d_in[7], (const float*)d_in[8],
        (const float*)d_in[9], (const float*)d_in[10], (const float*)d_in[11], (const float*)d_in[12],
        (const float*)d_in[13], (const float*)d_in[14], (const float*)d_in[15], (const float*)d_in[16],
        (const float*)d_in[17], (const float*)d_in[18],
        (float*)d_out);
}

// round 13
// speedup vs baseline: 1.0619x; 1.0184x over previous
#include <cuda_runtime.h>
#include <cuda_fp16.h>
#include <cstdint>

#define B_ 16384
#define S_ 336
#define T_ 48
#define NCTA_ 148
#define THREADS_ 512
#define MAXBLK_ 7

// smem byte offsets
#define H0A_ 0
#define H0B_ 16384
#define H1A_ 32768
#define H1B_ 49152
#define WHH0_ 65536
#define W1A_ 98304
#define W1B_ 131072
#define W0X_ 163840      // 256*48
#define XT0_ 176128      // 128*48
#define XT1_ 182272      // 128*48
#define BIAS0_ 188416    // 1024
#define BIAS1_ 189440    // 1024
#define PART_ 190464     // 128*8 floats = 4096
#define SMEM_BYTES 194560

__device__ __forceinline__ uint32_t smem_u32(const void* p) {
    uint32_t a;
    asm("{ .reg .u64 t; cvta.to.shared.u64 t, %1; cvt.u32.u64 %0, t; }" : "=r"(a) : "l"(p));
    return a;
}
__device__ __forceinline__ void sts32(uint32_t a, uint32_t v) {
    asm volatile("st.shared.u32 [%0], %1;" :: "r"(a), "r"(v) : "memory");
}
#define LDSM4(r0, r1, r2, r3, addr) \
    asm volatile("ldmatrix.sync.aligned.m8n8.x4.shared.b16 {%0,%1,%2,%3}, [%4];" \
        : "=r"(r0), "=r"(r1), "=r"(r2), "=r"(r3) : "r"(addr))

__device__ __forceinline__ void mma16816(float* d, uint32_t a0, uint32_t a1, uint32_t a2, uint32_t a3,
                                         uint32_t b0, uint32_t b1) {
    asm volatile(
        "mma.sync.aligned.m16n8k16.row.col.f32.f16.f16.f32 "
        "{%0,%1,%2,%3},{%4,%5,%6,%7},{%8,%9},{%0,%1,%2,%3};"
        : "+f"(d[0]), "+f"(d[1]), "+f"(d[2]), "+f"(d[3])
        : "r"(a0), "r"(a1), "r"(a2), "r"(a3), "r"(b0), "r"(b1));
}

__device__ __forceinline__ float tanh_a(float x) { float y; asm("tanh.approx.f32 %0,%1;" : "=f"(y) : "f"(x)); return y; }
__device__ __forceinline__ float sig_a(float x) { return fmaf(tanh_a(0.5f * x), 0.5f, 0.5f); }

// permuted gate row: smem row n -> source gate ((n>>3)&3)*64 + (n>>5)*8 + (n&7)
__device__ __forceinline__ int perm_gate(int n) {
    return ((n >> 3) & 3) * 64 + (n >> 5) * 8 + (n & 7);
}

// [256][64] fp16 tile, 128B rows, chunk swizzle c^(row&7), from fp32 row-major [256][64]
__device__ __forceinline__ void fill_wtile(uint32_t dst, const float* __restrict__ W) {
    for (int i = threadIdx.x; i < 256 * 32; i += THREADS_) {
        int n = i >> 5, p = i & 31;
        int gate = perm_gate(n);
        float2 v = *(const float2*)(W + gate * 64 + 2 * p);
        __half2 h = __floats2half2_rn(v.x, v.y);
        int chunk = p >> 2;
        sts32(dst + n * 128 + ((chunk ^ (n & 7)) << 4) + ((p & 3) << 2), *(uint32_t*)&h);
    }
}
// [256][16] fp16 tile, 48B row stride, first `incols` cols from W [256][incols], rest 0
__device__ __forceinline__ void fill_w0x(uint32_t dst, const float* __restrict__ W, int incols) {
    for (int i = threadIdx.x; i < 256 * 8; i += THREADS_) {
        int n = i >> 3, p = i & 7;
        int gate = perm_gate(n);
        int k0 = 2 * p, k1 = 2 * p + 1;
        float v0 = (k0 < incols) ? W[gate * incols + k0] : 0.0f;
        float v1 = (k1 < incols) ? W[gate * incols + k1] : 0.0f;
        __half2 h = __floats2half2_rn(v0, v1);
        sts32(dst + n * 48 + p * 4, *(uint32_t*)&h);
    }
}

// persistent B fragments: [256x64] weight tile -> 32 regs (this warp's 8 units, 4 ksteps)
__device__ __forceinline__ void load_bh(uint32_t wbase, uint32_t* bf, int ng, int lane) {
    const int mat = lane >> 3;
    const int brow = 32 * ng + 8 * (mat >> 1) + (lane & 7);
    const int bxor = lane & 7;
    const int bch = mat & 1;
#pragma unroll
    for (int ks = 0; ks < 4; ks++) {
        uint32_t aA = wbase + brow * 128 + (((2 * ks + bch) ^ bxor) << 4);
        LDSM4(bf[ks * 8 + 0], bf[ks * 8 + 1], bf[ks * 8 + 2], bf[ks * 8 + 3], aA);
        uint32_t aB = wbase + (brow + 16) * 128 + (((2 * ks + bch) ^ bxor) << 4);
        LDSM4(bf[ks * 8 + 4], bf[ks * 8 + 5], bf[ks * 8 + 6], bf[ks * 8 + 7], aB);
    }
}
// x-weight tile [256x16] -> 8 regs
__device__ __forceinline__ void load_bx(uint32_t wbase, uint32_t* bf, int ng, int lane) {
    const int mat = lane >> 3;
    const int brow = 32 * ng + 8 * (mat >> 1) + (lane & 7);
    const int bch = mat & 1;
    uint32_t aA = wbase + brow * 48 + bch * 16;
    LDSM4(bf[0], bf[1], bf[2], bf[3], aA);
    uint32_t aB = wbase + (brow + 16) * 48 + bch * 16;
    LDSM4(bf[4], bf[5], bf[6], bf[7], aB);
}

// shared fp32 epilogue for one 4-cell group (proven path; only h store is half)
template <bool FC>
__device__ __forceinline__ void epi_cells(float (&a)[4][4], float* c4, int mi,
                                          uint32_t hwr, int ng, int lane,
                                          float fw0, float fw1, float* part) {
    float h[4];
#pragma unroll
    for (int d = 0; d < 4; d++) {
        float i_ = sig_a(a[0][d]);
        float f_ = sig_a(a[1][d]);
        float g_ = tanh_a(a[2][d]);
        float o_ = sig_a(a[3][d]);
        float c = fmaf(f_, c4[d], i_ * g_);
        c4[d] = c;
        h[d] = o_ * tanh_a(c);
    }
    uint32_t cx = ((uint32_t)(ng ^ ((lane >> 2) & 7))) << 4;
    uint32_t ba = hwr + (mi * 16 + (lane >> 2)) * 128 + cx + (lane & 3) * 4;
    __half2 p1 = __floats2half2_rn(h[0], h[1]);
    sts32(ba, *(uint32_t*)&p1);
    __half2 p2 = __floats2half2_rn(h[2], h[3]);
    sts32(ba + 8 * 128, *(uint32_t*)&p2);
    if (FC) {
        float pA = fmaf(h[0], fw0, h[1] * fw1);
        float pB = fmaf(h[2], fw0, h[3] * fw1);
        pA += __shfl_xor_sync(0xffffffffu, pA, 1);
        pA += __shfl_xor_sync(0xffffffffu, pA, 2);
        pB += __shfl_xor_sync(0xffffffffu, pB, 1);
        pB += __shfl_xor_sync(0xffffffffu, pB, 2);
        if ((lane & 3) == 0) {
            int r = mi * 16 + (lane >> 2);
            part[r * 8 + ng] = pA;
            part[(r + 8) * 8 + ng] = pB;
        }
    }
}

// one layer tick over blocks [0, nblk), software-pipelined, double-buffered acc.
template <bool XPART, bool FC>
__device__ __forceinline__ void lstm_tick(uint32_t a1base, uint32_t a2base,
                                          const uint32_t* bf1, const uint32_t* bf2x,
                                          uint32_t w2base,
                                          uint32_t hwr, const float* biasp, float* cst,
                                          int ng, int lane, int nblk,
                                          float fw0, float fw1, float* part) {
    const int rowp = lane & 15;
    const int kh = lane >> 4;
    const int uA = 8 * ng + (lane & 3) * 2;
    const int mat = lane >> 3;
    const int brow = 32 * ng + 8 * (mat >> 1) + (lane & 7);
    const int bxor = lane & 7;
    const int bch = mat & 1;

    float accA[4][4], accB[4][4];

    auto init_acc = [&](float (&a)[4][4]) {
#pragma unroll
        for (int g = 0; g < 4; g++) {
            float2 bv = *(const float2*)(biasp + g * 64 + uA);
            a[g][0] = bv.x; a[g][1] = bv.y;
            a[g][2] = bv.x; a[g][3] = bv.y;
        }
    };

    auto mma_block = [&](int mi, float (&a)[4][4]) {
        const int rowbase = mi * 16;
        uint32_t a0, a1, a2, a3;
#pragma unroll
        for (int ks = 0; ks < 4; ks++) {
            uint32_t aa = a1base + (rowbase + rowp) * 128 + (((2 * ks + kh) ^ (rowp & 7)) << 4);
            LDSM4(a0, a1, a2, a3, aa);
#pragma unroll
            for (int j = 0; j < 4; j++)
                mma16816(a[j], a0, a1, a2, a3, bf1[ks * 8 + j * 2], bf1[ks * 8 + j * 2 + 1]);
        }
        if (XPART) {
            uint32_t aa = a2base + (rowbase + rowp) * 48 + kh * 16;
            LDSM4(a0, a1, a2, a3, aa);
#pragma unroll
            for (int j = 0; j < 4; j++)
                mma16816(a[j], a0, a1, a2, a3, bf2x[j * 2], bf2x[j * 2 + 1]);
        } else {
#pragma unroll
            for (int ks = 0; ks < 4; ks++) {
                uint32_t aa = a2base + (rowbase + rowp) * 128 + (((2 * ks + kh) ^ (rowp & 7)) << 4);
                LDSM4(a0, a1, a2, a3, aa);
                uint32_t b0, b1, b2, b3, b4, b5, b6, b7;
                uint32_t wA = w2base + brow * 128 + (((2 * ks + bch) ^ bxor) << 4);
                LDSM4(b0, b1, b2, b3, wA);
                uint32_t wB = w2base + (brow + 16) * 128 + (((2 * ks + bch) ^ bxor) << 4);
                LDSM4(b4, b5, b6, b7, wB);
                mma16816(a[0], a0, a1, a2, a3, b0, b1);
                mma16816(a[1], a0, a1, a2, a3, b2, b3);
                mma16816(a[2], a0, a1, a2, a3, b4, b5);
                mma16816(a[3], a0, a1, a2, a3, b6, b7);
            }
        }
    };

    init_acc(accA);
    mma_block(0, accA);
#pragma unroll
    for (int p = 0; p < (MAXBLK_ + 1) / 2; p++) {
        const int b0 = 2 * p, b1 = 2 * p + 1, b2 = 2 * p + 2;
        if (b0 >= nblk) break;
        if (b1 < nblk) { init_acc(accB); mma_block(b1, accB); }
        epi_cells<FC>(accA, cst + 4 * b0, b0, hwr, ng, lane, fw0, fw1, part);
        if (b1 < nblk) {
            if (b2 < nblk) { init_acc(accA); mma_block(b2, accA); }
            epi_cells<FC>(accB, cst + 4 * b1, b1, hwr, ng, lane, fw0, fw1, part);
        }
    }
}

// one L1 block (mi) with BOTH B operands loaded inline (W1A, W1B) — run by L0 warps.
// Identical math/accumulation order to the L1 tick path -> bit-identical results.
template <bool FC>
__device__ __forceinline__ void l1_block_inline(uint32_t a1base /*h0*/, uint32_t a2base /*h1*/,
                                                uint32_t w1a, uint32_t w1b,
                                                uint32_t hwr, const float* biasp, float* c4,
                                                int ng, int lane, int mi,
                                                float fw0, float fw1, float* part) {
    const int rowp = lane & 15;
    const int kh = lane >> 4;
    const int uA = 8 * ng + (lane & 3) * 2;
    const int mat = lane >> 3;
    const int brow = 32 * ng + 8 * (mat >> 1) + (lane & 7);
    const int bxor = lane & 7;
    const int bch = mat & 1;
    const int rowbase = mi * 16;

    float a[4][4];
#pragma unroll
    for (int g = 0; g < 4; g++) {
        float2 bv = *(const float2*)(biasp + g * 64 + uA);
        a[g][0] = bv.x; a[g][1] = bv.y;
        a[g][2] = bv.x; a[g][3] = bv.y;
    }
    uint32_t a0, a1, a2, a3;
#pragma unroll
    for (int ks = 0; ks < 4; ks++) {  // operand 1: W1A x h0
        uint32_t aa = a1base + (rowbase + rowp) * 128 + (((2 * ks + kh) ^ (rowp & 7)) << 4);
        LDSM4(a0, a1, a2, a3, aa);
        uint32_t b0, b1, b2, b3, b4, b5, b6, b7;
        uint32_t wA = w1a + brow * 128 + (((2 * ks + bch) ^ bxor) << 4);
        LDSM4(b0, b1, b2, b3, wA);
        uint32_t wB = w1a + (brow + 16) * 128 + (((2 * ks + bch) ^ bxor) << 4);
        LDSM4(b4, b5, b6, b7, wB);
        mma16816(a[0], a0, a1, a2, a3, b0, b1);
        mma16816(a[1], a0, a1, a2, a3, b2, b3);
        mma16816(a[2], a0, a1, a2, a3, b4, b5);
        mma16816(a[3], a0, a1, a2, a3, b6, b7);
    }
#pragma unroll
    for (int ks = 0; ks < 4; ks++) {  // operand 2: W1B x h1
        uint32_t aa = a2base + (rowbase + rowp) * 128 + (((2 * ks + kh) ^ (rowp & 7)) << 4);
        LDSM4(a0, a1, a2, a3, aa);
        uint32_t b0, b1, b2, b3, b4, b5, b6, b7;
        uint32_t wA = w1b + brow * 128 + (((2 * ks + bch) ^ bxor) << 4);
        LDSM4(b0, b1, b2, b3, wA);
        uint32_t wB = w1b + (brow + 16) * 128 + (((2 * ks + bch) ^ bxor) << 4);
        LDSM4(b4, b5, b6, b7, wB);
        mma16816(a[0], a0, a1, a2, a3, b0, b1);
        mma16816(a[1], a0, a1, a2, a3, b2, b3);
        mma16816(a[2], a0, a1, a2, a3, b4, b5);
        mma16816(a[3], a0, a1, a2, a3, b6, b7);
    }
    epi_cells<FC>(a, c4, mi, hwr, ng, lane, fw0, fw1, part);
}

__global__ void __launch_bounds__(THREADS_, 1)
seq2seq_pipe(const float* __restrict__ src,
             const float* __restrict__ eWih0, const float* __restrict__ eWhh0,
             const float* __restrict__ ebih0, const float* __restrict__ ebhh0,
             const float* __restrict__ eWih1, const float* __restrict__ eWhh1,
             const float* __restrict__ ebih1, const float* __restrict__ ebhh1,
             const float* __restrict__ dWih0, const float* __restrict__ dWhh0,
             const float* __restrict__ dbih0, const float* __restrict__ dbhh0,
             const float* __restrict__ dWih1, const float* __restrict__ dWhh1,
             const float* __restrict__ dbih1, const float* __restrict__ dbhh1,
             const float* __restrict__ fcW, const float* __restrict__ fcb,
             float* __restrict__ out) {
    extern __shared__ char smc[];
    const uint32_t sb = smem_u32(smc);
    const int tid = threadIdx.x;
    const int lane = tid & 31;
    const int warp = tid >> 5;
    const bool isL0 = warp < 8;
    const int ng = isL0 ? warp : warp - 8;
    // uneven persistent grid: 1024 row-blocks = 136 CTAs x 7 + 12 CTAs x 6
    const int bid = blockIdx.x;
    const int nblk = (bid < 136) ? 7 : 6;
    const int row0 = (bid < 136) ? bid * 112 : 136 * 112 + (bid - 136) * 96;
    const int rows = nblk * 16;
    const int xblk = nblk - 1;  // L1 block moved to L0 warps

    // zero h buffers and XT buffers
    {
        uint4 z = make_uint4(0, 0, 0, 0);
        uint4* p0 = (uint4*)smc;
        for (int i = tid; i < 65536 / 16; i += THREADS_) p0[i] = z;
        uint4* p1 = (uint4*)(smc + XT0_);
        for (int i = tid; i < 12288 / 16; i += THREADS_) p1[i] = z;
    }
    __syncthreads();

    fill_wtile(sb + WHH0_, eWhh0);
    fill_wtile(sb + W1A_, eWih1);
    fill_wtile(sb + W1B_, eWhh1);
    fill_w0x(sb + W0X_, eWih0, 5);
    for (int i = tid; i < 256; i += THREADS_) {
        ((float*)(smc + BIAS0_))[i] = __ldg(ebih0 + i) + __ldg(ebhh0 + i);
        ((float*)(smc + BIAS1_))[i] = __ldg(ebih1 + i) + __ldg(ebhh1 + i);
    }
    const float* srcRow = src + (size_t)(row0 + tid) * S_ * 5;
    if (tid < rows) {  // x(0) -> XT0
        uint32_t xb = sb + XT0_ + tid * 48;
        __half2 a01 = __floats2half2_rn(__ldg(srcRow + 0), __ldg(srcRow + 1));
        __half2 a23 = __floats2half2_rn(__ldg(srcRow + 2), __ldg(srcRow + 3));
        __half2 a4z = __floats2half2_rn(__ldg(srcRow + 4), 0.0f);
        sts32(xb, *(uint32_t*)&a01);
        sts32(xb + 4, *(uint32_t*)&a23);
        sts32(xb + 8, *(uint32_t*)&a4z);
    }
    __syncthreads();

    // persistent weight fragments: bf1 hoisted; bf2 hoisted only for L0 (x-weights)
    uint32_t bf1[32], bf2x[8];
    if (isL0) {
        load_bh(sb + WHH0_, bf1, ng, lane);
        load_bx(sb + W0X_, bf2x, ng, lane);
    } else {
        load_bh(sb + W1A_, bf1, ng, lane);
    }

    // c-state: L0 warp holds c0 for all nblk blocks + c1 for block xblk (cstx).
    //          L1 warp holds c1 for blocks [0, xblk).
    float cst[4 * MAXBLK_];
    float cstx[4];
#pragma unroll
    for (int j = 0; j < 4 * MAXBLK_; j++) cst[j] = 0.0f;
#pragma unroll
    for (int j = 0; j < 4; j++) cstx[j] = 0.0f;

    const float* bias0 = (const float*)(smc + BIAS0_);
    const float* bias1 = (const float*)(smc + BIAS1_);

    // ============ encoder pipeline: ticks k=0..S ============
    for (int k = 0; k <= S_; k++) {
        const uint32_t h0r = sb + ((k & 1) ? H0A_ : H0B_);
        const uint32_t h0w = sb + ((k & 1) ? H0B_ : H0A_);
        const uint32_t h1r = sb + ((k & 1) ? H1B_ : H1A_);
        const uint32_t h1w = sb + ((k & 1) ? H1A_ : H1B_);
        const uint32_t xtr = sb + ((k & 1) ? XT1_ : XT0_);
        const uint32_t xtw = sb + ((k & 1) ? XT0_ : XT1_);

        float x0, x1, x2, x3, x4;
        const bool pf = (tid < rows) && (k + 1 < S_);
        if (pf) {
            const float* xp = srcRow + (size_t)(k + 1) * 5;
            x0 = __ldg(xp + 0); x1 = __ldg(xp + 1); x2 = __ldg(xp + 2);
            x3 = __ldg(xp + 3); x4 = __ldg(xp + 4);
        }
        if (isL0) {
            if (k < S_)
                lstm_tick<true, false>(h0r, xtr, bf1, bf2x, 0, h0w, bias0, cst, ng, lane, nblk, 0.f, 0.f, nullptr);
            if (k >= 1)
                l1_block_inline<false>(h0r, h1r, sb + W1A_, sb + W1B_, h1w, bias1, cstx, ng, lane, xblk, 0.f, 0.f, nullptr);
        } else {
            if (k >= 1)
                lstm_tick<false, false>(h0r, h1r, bf1, nullptr, sb + W1B_, h1w, bias1, cst, ng, lane, xblk, 0.f, 0.f, nullptr);
        }
        if (pf) {
            __half2 a01 = __floats2half2_rn(x0, x1);
            __half2 a23 = __floats2half2_rn(x2, x3);
            __half2 a4z = __floats2half2_rn(x4, 0.0f);
            uint32_t xb = xtw + tid * 48;
            sts32(xb, *(uint32_t*)&a01);
            sts32(xb + 4, *(uint32_t*)&a23);
            sts32(xb + 8, *(uint32_t*)&a4z);
        }
        __syncthreads();
    }

    // ============ decoder weight swap ============
    fill_wtile(sb + WHH0_, dWhh0);
    fill_wtile(sb + W1A_, dWih1);
    fill_wtile(sb + W1B_, dWhh1);
    fill_w0x(sb + W0X_, dWih0, 1);
    for (int i = tid; i < 256; i += THREADS_) {
        ((float*)(smc + BIAS0_))[i] = __ldg(dbih0 + i) + __ldg(dbhh0 + i);
        ((float*)(smc + BIAS1_))[i] = __ldg(dbih1 + i) + __ldg(dbhh1 + i);
    }
    {
        uint4 z = make_uint4(0, 0, 0, 0);
        uint4* p1 = (uint4*)(smc + XT0_);
        for (int i = tid; i < 12288 / 16; i += THREADS_) p1[i] = z;
    }
    // fc weights for ALL warps (L0 warps do the moved L1 block's fc partial)
    const int uAa = 8 * ng + (lane & 3) * 2;
    const float fw0 = __ldg(fcW + uAa);
    const float fw1 = __ldg(fcW + uAa + 1);
    const float fcb_r = __ldg(fcb);
    __syncthreads();

    if (isL0) {
        load_bh(sb + WHH0_, bf1, ng, lane);
        load_bx(sb + W0X_, bf2x, ng, lane);
    } else {
        load_bh(sb + W1A_, bf1, ng, lane);
    }
    if (tid < rows) {  // x(0) = src[:, -1, 3] -> XT0
        float xd = __ldg(srcRow + (size_t)(S_ - 1) * 5 + 3);
        __half2 hx = __floats2half2_rn(xd, 0.0f);
        sts32(sb + XT0_ + tid * 48, *(uint32_t*)&hx);
    }
    __syncthreads();

    float* part = (float*)(smc + PART_);

    // ============ decoder: sequential phases ============
    for (int t = 0; t < T_; t++) {
        const uint32_t h0r = sb + ((t & 1) ? H0A_ : H0B_);
        const uint32_t h0w = sb + ((t & 1) ? H0B_ : H0A_);
        const uint32_t h1r = sb + ((t & 1) ? H1A_ : H1B_);
        const uint32_t h1w = sb + ((t & 1) ? H1B_ : H1A_);
        const uint32_t xtr = sb + ((t & 1) ? XT1_ : XT0_);

        if (isL0)
            lstm_tick<true, false>(h0r, xtr, bf1, bf2x, 0, h0w, bias0, cst, ng, lane, nblk, 0.f, 0.f, nullptr);
        __syncthreads();
        if (!isL0)
            lstm_tick<false, true>(h0w, h1r, bf1, nullptr, sb + W1B_, h1w, bias1, cst, ng, lane, xblk, fw0, fw1, part);
        else
            l1_block_inline<true>(h0w, h1r, sb + W1A_, sb + W1B_, h1w, bias1, cstx, ng, lane, xblk, fw0, fw1, part);
        __syncthreads();
        if (tid < rows) {
            float4 q0 = *(float4*)(part + tid * 8);
            float4 q1 = *(float4*)(part + tid * 8 + 4);
            float x = q0.x + q0.y + q0.z + q0.w + q1.x + q1.y + q1.z + q1.w + fcb_r;
            out[(size_t)(row0 + tid) * T_ + t] = x;
            __half2 hx = __floats2half2_rn(x, 0.0f);
            sts32(sb + ((t & 1) ? XT0_ : XT1_) + tid * 48, *(uint32_t*)&hx);
        }
        __syncthreads();
    }
}

extern "C" void kernel_launch(void* const* d_in, const int* in_sizes, int n_in,
                              void* d_out, int out_size) {
    (void)in_sizes; (void)n_in; (void)out_size;
    cudaFuncSetAttribute(seq2seq_pipe, cudaFuncAttributeMaxDynamicSharedMemorySize, SMEM_BYTES);
    seq2seq_pipe<<<NCTA_, THREADS_, SMEM_BYTES>>>(
        (const float*)d_in[0],
        (const float*)d_in[1], (const float*)d_in[2], (const float*)d_in[3], (const float*)d_in[4],
        (const float*)d_in[5], (const float*)d_in[6], (const float*)d_in[7], (const float*)d_in[8],
        (const float*)d_in[9], (const float*)d_in[10], (const float*)d_in[11], (const float*)d_in[12],
        (const float*)d_in[13], (const float*)d_in[14], (const float*)d_in[15], (const float*)d_in[16],
        (const float*)d_in[17], (const float*)d_in[18],
        (float*)d_out);
}